// round 1
// baseline (speedup 1.0000x reference)
#include <cuda_runtime.h>
#include <math.h>

#define NVEC 12
#define CIN  8
#define COUT 8
#define DIM  64
#define VOX  (DIM*DIM*DIM)      // 262144
#define CH   (CIN*NVEC)         // 96

// Device-global scratch (allocation-free per harness rules)
__device__ float g_sw[CH * 125];          // depthwise taps: [c][k], c=f*12+v, k=kx*25+ky*5+kz
__device__ float g_fwm[CH * CH];          // mixing matrix: [oc][fv], oc=g*12+w, fv=f*12+v
__device__ float g_y[(size_t)2 * CH * VOX];  // depthwise conv output (192 MiB)

__device__ __forceinline__ float gelu_exact(float v) {
    return 0.5f * v * (1.0f + erff(v * 0.70710678118654752440f));
}

// ---------------------------------------------------------------------------
// Kernel W: tiny MLPs that generate the conv taps and the mixing matrix.
// ---------------------------------------------------------------------------
__global__ void weights_kernel(
    const float* __restrict__ sp,   // [1500,2]
    const float* __restrict__ sph,  // [144,1]
    const float* __restrict__ bw1, const float* __restrict__ bb1,
    const float* __restrict__ bw2, const float* __restrict__ bb2,
    const float* __restrict__ bw3,
    const float* __restrict__ fw1, const float* __restrict__ fb1,
    const float* __restrict__ fw2, const float* __restrict__ fb2,
    const float* __restrict__ fw3)
{
    // --- spatial basis MLP: 14 -> 8 -> 8 -> CIN, rows = K^3 * NV = 1500 ---
    for (int r = threadIdx.x; r < 1500; r += blockDim.x) {
        float s0 = sp[2 * r], s1 = sp[2 * r + 1];
        float a[14];
        a[0] = s0; a[1] = s1;
        a[2] = s0 * s0; a[3] = s0 * s1; a[4] = s1 * s0; a[5] = s1 * s1;
        #pragma unroll
        for (int i = 0; i < 4; i++) { a[6 + 2*i] = a[2 + i] * s0; a[7 + 2*i] = a[2 + i] * s1; }
        float h1[8], h2[8];
        #pragma unroll
        for (int j = 0; j < 8; j++) {
            float s = bb1[j];
            #pragma unroll
            for (int i = 0; i < 14; i++) s += bw1[j * 14 + i] * a[i];
            h1[j] = gelu_exact(s);
        }
        #pragma unroll
        for (int j = 0; j < 8; j++) {
            float s = bb2[j];
            #pragma unroll
            for (int i = 0; i < 8; i++) s += bw2[j * 8 + i] * h1[i];
            h2[j] = gelu_exact(s);
        }
        int k = r / 12, v = r % 12;
        #pragma unroll
        for (int f = 0; f < 8; f++) {
            float o = 0.f;
            #pragma unroll
            for (int i = 0; i < 8; i++) o += bw3[f * 8 + i] * h2[i];
            g_sw[(f * 12 + v) * 125 + k] = o;
        }
    }
    // --- fiber MLP: 3 -> 8 -> 8 -> CIN*COUT, rows = NV*NV = 144 ---
    for (int r = threadIdx.x; r < 144; r += blockDim.x) {
        float c0 = sph[r];
        float a0 = c0, a1 = c0 * c0, a2 = c0 * c0 * c0;
        float h1[8], h2[8];
        #pragma unroll
        for (int j = 0; j < 8; j++) {
            float s = fb1[j] + fw1[j*3+0]*a0 + fw1[j*3+1]*a1 + fw1[j*3+2]*a2;
            h1[j] = gelu_exact(s);
        }
        #pragma unroll
        for (int j = 0; j < 8; j++) {
            float s = fb2[j];
            #pragma unroll
            for (int i = 0; i < 8; i++) s += fw2[j * 8 + i] * h1[i];
            h2[j] = gelu_exact(s);
        }
        int v = r / 12, w = r % 12;
        #pragma unroll
        for (int col = 0; col < 64; col++) {
            float o = 0.f;
            #pragma unroll
            for (int i = 0; i < 8; i++) o += fw3[col * 8 + i] * h2[i];
            int f = col >> 3, g = col & 7;
            // out[b,g,w,p] += y[b,f,v,p] * fwm[oc=g*12+w][fv=f*12+v]
            g_fwm[(g * 12 + w) * CH + (f * 12 + v)] = o;
        }
    }
}

// ---------------------------------------------------------------------------
// Kernel A: depthwise 5x5x5 conv (cross-correlation, SAME padding).
// One block per (8^3 spatial tile, channel, batch). Threads compute 4-long
// z-columns from a 12^3 smem tile with float4 smem reads.
// ---------------------------------------------------------------------------
__global__ __launch_bounds__(128) void conv_kernel(const float* __restrict__ x)
{
    __shared__ __align__(16) float s_x[12 * 12 * 12];  // 1728
    __shared__ __align__(16) float s_k[25 * 8];        // taps padded to 8/row

    int tile = blockIdx.x;            // 0..511
    int c    = blockIdx.y;            // 0..95
    int b    = blockIdx.z;            // 0..1
    int tz = tile & 7, ty = (tile >> 3) & 7, tx = tile >> 6;
    int t = threadIdx.x;

    const float* xb = x + (size_t)(b * CH + c) * VOX;
    int gx0 = tx * 8 - 2, gy0 = ty * 8 - 2, gz0 = tz * 8 - 2;

    for (int i = t; i < 1728; i += 128) {
        int lx = i / 144, rr = i % 144, ly = rr / 12, lz = rr % 12;
        int gx = gx0 + lx, gy = gy0 + ly, gz = gz0 + lz;
        float vv = 0.f;
        if ((unsigned)gx < 64u && (unsigned)gy < 64u && (unsigned)gz < 64u)
            vv = xb[(gx << 12) + (gy << 6) + gz];
        s_x[i] = vv;
    }
    if (t < 125) {
        int kx = t / 25, rr = t % 25, ky = rr / 5, kz = rr % 5;
        s_k[(kx * 5 + ky) * 8 + kz] = g_sw[c * 125 + t];
    }
    __syncthreads();

    int ox = t >> 4;
    int oy = (t >> 1) & 7;
    int z0 = (t & 1) * 4;

    float a0 = 0.f, a1 = 0.f, a2 = 0.f, a3 = 0.f;
    #pragma unroll
    for (int kx = 0; kx < 5; kx++) {
        #pragma unroll
        for (int ky = 0; ky < 5; ky++) {
            const float* xp = &s_x[((ox + kx) * 12 + (oy + ky)) * 12 + z0];
            float4 va = *(const float4*)xp;
            float4 vb = *(const float4*)(xp + 4);
            float xs0 = va.x, xs1 = va.y, xs2 = va.z, xs3 = va.w;
            float xs4 = vb.x, xs5 = vb.y, xs6 = vb.z, xs7 = vb.w;
            const float* kp = &s_k[(kx * 5 + ky) * 8];
            float4 tt = *(const float4*)kp;
            float t4 = kp[4];
            a0 += xs0*tt.x + xs1*tt.y + xs2*tt.z + xs3*tt.w + xs4*t4;
            a1 += xs1*tt.x + xs2*tt.y + xs3*tt.z + xs4*tt.w + xs5*t4;
            a2 += xs2*tt.x + xs3*tt.y + xs4*tt.z + xs5*tt.w + xs6*t4;
            a3 += xs3*tt.x + xs4*tt.y + xs5*tt.z + xs6*tt.w + xs7*t4;
        }
    }
    size_t oidx = (size_t)(b * CH + c) * VOX
                + (size_t)((tx * 8 + ox) << 12) + ((ty * 8 + oy) << 6) + tz * 8 + z0;
    *(float4*)&g_y[oidx] = make_float4(a0, a1, a2, a3);
}

// ---------------------------------------------------------------------------
// Kernel B: per-voxel 96x96 channel mixing + bias. Weights in smem (broadcast
// LDS.128), 96 register accumulators per thread (1 voxel/thread).
// ---------------------------------------------------------------------------
__global__ __launch_bounds__(128) void mix_kernel(
    const float* __restrict__ bias, float* __restrict__ out)
{
    __shared__ __align__(16) float s_w[CH * CH];  // 9216 floats = 36 KB
    __shared__ float s_b[CH];
    int t = threadIdx.x;

    for (int i = t * 4; i < CH * CH; i += 128 * 4)
        *(float4*)&s_w[i] = *(const float4*)&g_fwm[i];
    if (t < CH) s_b[t] = bias[t / 12];   // bias per g, oc = g*12+w
    __syncthreads();

    int vg = blockIdx.x * 128 + t;       // 0..524287
    int b  = vg >> 18;
    int p  = vg & (VOX - 1);
    const float* yb = g_y + (size_t)b * CH * VOX + p;

    float acc[CH];
    #pragma unroll
    for (int i = 0; i < CH; i++) acc[i] = 0.f;

    for (int fv = 0; fv < CH; fv += 4) {
        const float* yc = yb + (size_t)fv * VOX;
        float y0 = yc[0];
        float y1 = yc[(size_t)VOX];
        float y2 = yc[(size_t)2 * VOX];
        float y3 = yc[(size_t)3 * VOX];
        const float* wr = &s_w[fv];
        #pragma unroll
        for (int oc = 0; oc < CH; oc++) {
            float4 w4 = *(const float4*)&wr[oc * CH];
            acc[oc] += y0 * w4.x + y1 * w4.y + y2 * w4.z + y3 * w4.w;
        }
    }

    float* ob = out + (size_t)b * CH * VOX + p;
    #pragma unroll
    for (int oc = 0; oc < CH; oc++)
        ob[(size_t)oc * VOX] = acc[oc] + s_b[oc];
}

// ---------------------------------------------------------------------------
extern "C" void kernel_launch(void* const* d_in, const int* in_sizes, int n_in,
                              void* d_out, int out_size)
{
    const float* x    = (const float*)d_in[0];
    const float* sp   = (const float*)d_in[1];
    const float* sph  = (const float*)d_in[2];
    const float* bw1  = (const float*)d_in[3];
    const float* bb1  = (const float*)d_in[4];
    const float* bw2  = (const float*)d_in[5];
    const float* bb2  = (const float*)d_in[6];
    const float* bw3  = (const float*)d_in[7];
    const float* fw1  = (const float*)d_in[8];
    const float* fb1  = (const float*)d_in[9];
    const float* fw2  = (const float*)d_in[10];
    const float* fb2  = (const float*)d_in[11];
    const float* fw3  = (const float*)d_in[12];
    const float* bias = (const float*)d_in[13];

    weights_kernel<<<1, 256>>>(sp, sph, bw1, bb1, bw2, bb2, bw3,
                               fw1, fb1, fw2, fb2, fw3);

    dim3 gA(512, CH, 2);
    conv_kernel<<<gA, 128>>>(x);

    mix_kernel<<<4096, 128>>>(bias, (float*)d_out);
}

// round 2
// speedup vs baseline: 1.0469x; 1.0469x over previous
#include <cuda_runtime.h>
#include <math.h>

#define NVEC 12
#define CIN  8
#define COUT 8
#define DIM  64
#define VOX  (DIM*DIM*DIM)      // 262144
#define CH   (CIN*NVEC)         // 96

typedef unsigned long long ull;

// Device-global scratch (allocation-free per harness rules)
__device__ float g_sw[CH * 125];            // depthwise taps: [c][k]
__device__ float g_fwmT[CH * CH];           // mixing matrix TRANSPOSED: [fv][oc]
__device__ float g_y[(size_t)2 * CH * VOX]; // depthwise conv output (192 MiB)

__device__ __forceinline__ float gelu_exact(float v) {
    return 0.5f * v * (1.0f + erff(v * 0.70710678118654752440f));
}

// ---- packed f32x2 helpers ----
__device__ __forceinline__ void fma2(ull& d, ull a, ull b) {
    asm("fma.rn.f32x2 %0, %1, %2, %0;" : "+l"(d) : "l"(a), "l"(b));
}
__device__ __forceinline__ ull pack2(float lo, float hi) {
    ull d;
    asm("mov.b64 %0, {%1, %2};" : "=l"(d) : "f"(lo), "f"(hi));
    return d;
}
// pair (hi(a), lo(b))
__device__ __forceinline__ ull mkpair(ull a, ull b) {
    unsigned int lo = (unsigned int)(a >> 32);
    unsigned int hi = (unsigned int)(b & 0xFFFFFFFFull);
    ull d;
    asm("mov.b64 %0, {%1, %2};" : "=l"(d) : "r"(lo), "r"(hi));
    return d;
}
__device__ __forceinline__ float2 asf2(ull v) {
    float2 r;
    asm("mov.b64 {%0, %1}, %2;" : "=f"(r.x), "=f"(r.y) : "l"(v));
    return r;
}

// ---------------------------------------------------------------------------
// Kernel W: tiny MLPs that generate the conv taps and the mixing matrix.
// Parallelized across 16 blocks (was a 30us single-block serialization).
// ---------------------------------------------------------------------------
__global__ void weights_kernel(
    const float* __restrict__ sp,   // [1500,2]
    const float* __restrict__ sph,  // [144,1]
    const float* __restrict__ bw1, const float* __restrict__ bb1,
    const float* __restrict__ bw2, const float* __restrict__ bb2,
    const float* __restrict__ bw3,
    const float* __restrict__ fw1, const float* __restrict__ fb1,
    const float* __restrict__ fw2, const float* __restrict__ fb2,
    const float* __restrict__ fw3)
{
    int tid0 = blockIdx.x * blockDim.x + threadIdx.x;
    int stride = gridDim.x * blockDim.x;

    // --- spatial basis MLP: 14 -> 8 -> 8 -> CIN, rows = K^3 * NV = 1500 ---
    for (int r = tid0; r < 1500; r += stride) {
        float s0 = sp[2 * r], s1 = sp[2 * r + 1];
        float a[14];
        a[0] = s0; a[1] = s1;
        a[2] = s0 * s0; a[3] = s0 * s1; a[4] = s1 * s0; a[5] = s1 * s1;
        #pragma unroll
        for (int i = 0; i < 4; i++) { a[6 + 2*i] = a[2 + i] * s0; a[7 + 2*i] = a[2 + i] * s1; }
        float h1[8], h2[8];
        #pragma unroll
        for (int j = 0; j < 8; j++) {
            float s = bb1[j];
            #pragma unroll
            for (int i = 0; i < 14; i++) s += bw1[j * 14 + i] * a[i];
            h1[j] = gelu_exact(s);
        }
        #pragma unroll
        for (int j = 0; j < 8; j++) {
            float s = bb2[j];
            #pragma unroll
            for (int i = 0; i < 8; i++) s += bw2[j * 8 + i] * h1[i];
            h2[j] = gelu_exact(s);
        }
        int k = r / 12, v = r % 12;
        #pragma unroll
        for (int f = 0; f < 8; f++) {
            float o = 0.f;
            #pragma unroll
            for (int i = 0; i < 8; i++) o += bw3[f * 8 + i] * h2[i];
            g_sw[(f * 12 + v) * 125 + k] = o;
        }
    }
    // --- fiber MLP: 3 -> 8 -> 8 -> CIN*COUT, rows = NV*NV = 144 ---
    for (int r = tid0; r < 144; r += stride) {
        float c0 = sph[r];
        float a0 = c0, a1 = c0 * c0, a2 = c0 * c0 * c0;
        float h1[8], h2[8];
        #pragma unroll
        for (int j = 0; j < 8; j++) {
            float s = fb1[j] + fw1[j*3+0]*a0 + fw1[j*3+1]*a1 + fw1[j*3+2]*a2;
            h1[j] = gelu_exact(s);
        }
        #pragma unroll
        for (int j = 0; j < 8; j++) {
            float s = fb2[j];
            #pragma unroll
            for (int i = 0; i < 8; i++) s += fw2[j * 8 + i] * h1[i];
            h2[j] = gelu_exact(s);
        }
        int v = r / 12, w = r % 12;
        #pragma unroll
        for (int col = 0; col < 64; col++) {
            float o = 0.f;
            #pragma unroll
            for (int i = 0; i < 8; i++) o += fw3[col * 8 + i] * h2[i];
            int f = col >> 3, g = col & 7;
            // TRANSPOSED store: [fv][oc]
            g_fwmT[(f * 12 + v) * CH + (g * 12 + w)] = o;
        }
    }
}

// ---------------------------------------------------------------------------
// Kernel A: depthwise 5x5x5 conv (cross-correlation, SAME padding), f32x2.
// One block = (8^3 spatial tile, 2 channels, batch). Each thread computes a
// full 8-long z-column as 4 packed f32x2 accumulators. Taps stored DUPLICATED
// {t,t} in smem so tap pairs come straight from broadcast LDS.
// ---------------------------------------------------------------------------
__global__ __launch_bounds__(128) void conv_kernel(const float* __restrict__ x)
{
    __shared__ __align__(16) float s_x[2 * 1728];        // 12^3 per channel
    __shared__ __align__(16) float s_k2[2 * 25 * 12];    // dup taps, 12f/pos

    int tile = blockIdx.x;            // 0..511
    int c0   = blockIdx.y * 2;        // channel pair base
    int b    = blockIdx.z;            // 0..1
    int tz = tile & 7, ty = (tile >> 3) & 7, tx = tile >> 6;
    int t = threadIdx.x;

    int gx0 = tx * 8 - 2, gy0 = ty * 8 - 2, gz0 = tz * 8 - 2;

    // halo load: 2 channels x 12^3
    for (int i = t; i < 3456; i += 128) {
        int cl = i / 1728;
        int r  = i - cl * 1728;
        int lx = r / 144, rr = r % 144, ly = rr / 12, lz = rr % 12;
        int gx = gx0 + lx, gy = gy0 + ly, gz = gz0 + lz;
        float vv = 0.f;
        if ((unsigned)gx < 64u && (unsigned)gy < 64u && (unsigned)gz < 64u)
            vv = x[(size_t)(b * CH + c0 + cl) * VOX + (gx << 12) + (gy << 6) + gz];
        s_x[i] = vv;
    }
    // duplicated taps: layout [cl][pos(25)][t0 t0 t1 t1 t2 t2 t3 t3 t4 t4 pad pad]
    for (int i = t; i < 250; i += 128) {
        int cl = (i >= 125) ? 1 : 0;
        int k  = i - cl * 125;
        float val = g_sw[(c0 + cl) * 125 + k];
        int kx = k / 25, rr = k % 25, ky = rr / 5, kz = rr % 5;
        int base = cl * 300 + (kx * 5 + ky) * 12 + kz * 2;
        s_k2[base] = val; s_k2[base + 1] = val;
    }
    __syncthreads();

    int cl = t >> 6;          // warps 0-1: ch0, warps 2-3: ch1 (uniform per warp)
    int xy = t & 63;
    int ox = xy >> 3, oy = xy & 7;

    const float* xc = &s_x[cl * 1728];
    const float* kc = &s_k2[cl * 300];

    ull a0 = 0, a1 = 0, a2 = 0, a3 = 0;
    #pragma unroll
    for (int kx = 0; kx < 5; kx++) {
        #pragma unroll
        for (int ky = 0; ky < 5; ky++) {
            const ulonglong2* xp = (const ulonglong2*)(xc + ((ox + kx) * 12 + (oy + ky)) * 12);
            ulonglong2 eA = xp[0];   // (xs0,xs1) (xs2,xs3)
            ulonglong2 eB = xp[1];   // (xs4,xs5) (xs6,xs7)
            ulonglong2 eC = xp[2];   // (xs8,xs9) (xs10,xs11)
            const ulonglong2* kp = (const ulonglong2*)(kc + (kx * 5 + ky) * 12);
            ulonglong2 kA = kp[0];   // T0 T1
            ulonglong2 kB = kp[1];   // T2 T3
            ull T4 = *(const ull*)(kc + (kx * 5 + ky) * 12 + 8);

            ull o0 = mkpair(eA.x, eA.y);  // (xs1,xs2)
            ull o1 = mkpair(eA.y, eB.x);  // (xs3,xs4)
            ull o2 = mkpair(eB.x, eB.y);  // (xs5,xs6)
            ull o3 = mkpair(eB.y, eC.x);  // (xs7,xs8)
            ull o4 = mkpair(eC.x, eC.y);  // (xs9,xs10)

            fma2(a0, eA.x, kA.x); fma2(a1, eA.y, kA.x); fma2(a2, eB.x, kA.x); fma2(a3, eB.y, kA.x);
            fma2(a0, o0,   kA.y); fma2(a1, o1,   kA.y); fma2(a2, o2,   kA.y); fma2(a3, o3,   kA.y);
            fma2(a0, eA.y, kB.x); fma2(a1, eB.x, kB.x); fma2(a2, eB.y, kB.x); fma2(a3, eC.x, kB.x);
            fma2(a0, o1,   kB.y); fma2(a1, o2,   kB.y); fma2(a2, o3,   kB.y); fma2(a3, o4,   kB.y);
            fma2(a0, eB.x, T4);   fma2(a1, eB.y, T4);   fma2(a2, eC.x, T4);   fma2(a3, eC.y, T4);
        }
    }

    size_t oidx = (size_t)(b * CH + c0 + cl) * VOX
                + (size_t)((tx * 8 + ox) << 12) + ((ty * 8 + oy) << 6) + tz * 8;
    float2 f0 = asf2(a0), f1 = asf2(a1), f2 = asf2(a2), f3 = asf2(a3);
    *(float4*)&g_y[oidx]     = make_float4(f0.x, f0.y, f1.x, f1.y);
    *(float4*)&g_y[oidx + 4] = make_float4(f2.x, f2.y, f3.x, f3.y);
}

// ---------------------------------------------------------------------------
// Kernel B: per-voxel 96x96 channel mixing + bias, f32x2.
// Transposed weights [fv][oc] in smem: one broadcast LDS.128 -> two ready
// (w[oc],w[oc+1]) pairs. 48 packed accumulators cover all 96 out-channels.
// ---------------------------------------------------------------------------
__global__ __launch_bounds__(128) void mix_kernel(
    const float* __restrict__ bias, float* __restrict__ out)
{
    __shared__ __align__(16) float s_wT[CH * CH];  // [fv][oc], 36 KB
    __shared__ float s_b[CH];
    int t = threadIdx.x;

    for (int i = t * 4; i < CH * CH; i += 128 * 4)
        *(float4*)&s_wT[i] = *(const float4*)&g_fwmT[i];
    if (t < CH) s_b[t] = bias[t / 12];
    __syncthreads();

    int vg = blockIdx.x * 128 + t;       // 0..524287
    int b  = vg >> 18;
    int p  = vg & (VOX - 1);
    const float* yb = g_y + (size_t)b * CH * VOX + p;

    ull acc[48];
    #pragma unroll
    for (int i = 0; i < 48; i++) acc[i] = 0ull;

    for (int fv = 0; fv < CH; fv += 4) {
        float y0 = yb[(size_t)(fv + 0) * VOX];
        float y1 = yb[(size_t)(fv + 1) * VOX];
        float y2 = yb[(size_t)(fv + 2) * VOX];
        float y3 = yb[(size_t)(fv + 3) * VOX];
        ull yy0 = pack2(y0, y0), yy1 = pack2(y1, y1);
        ull yy2 = pack2(y2, y2), yy3 = pack2(y3, y3);

        const ulonglong2* w0 = (const ulonglong2*)&s_wT[(size_t)(fv + 0) * CH];
        const ulonglong2* w1 = (const ulonglong2*)&s_wT[(size_t)(fv + 1) * CH];
        const ulonglong2* w2 = (const ulonglong2*)&s_wT[(size_t)(fv + 2) * CH];
        const ulonglong2* w3 = (const ulonglong2*)&s_wT[(size_t)(fv + 3) * CH];
        #pragma unroll
        for (int j = 0; j < 24; j++) {
            ulonglong2 wa = w0[j];
            fma2(acc[2*j],   yy0, wa.x); fma2(acc[2*j+1], yy0, wa.y);
            ulonglong2 wb = w1[j];
            fma2(acc[2*j],   yy1, wb.x); fma2(acc[2*j+1], yy1, wb.y);
            ulonglong2 wc = w2[j];
            fma2(acc[2*j],   yy2, wc.x); fma2(acc[2*j+1], yy2, wc.y);
            ulonglong2 wd = w3[j];
            fma2(acc[2*j],   yy3, wd.x); fma2(acc[2*j+1], yy3, wd.y);
        }
    }

    float* ob = out + (size_t)b * CH * VOX + p;
    #pragma unroll
    for (int j = 0; j < 48; j++) {
        float2 v = asf2(acc[j]);
        ob[(size_t)(2*j)     * VOX] = v.x + s_b[2*j];
        ob[(size_t)(2*j + 1) * VOX] = v.y + s_b[2*j + 1];
    }
}

// ---------------------------------------------------------------------------
extern "C" void kernel_launch(void* const* d_in, const int* in_sizes, int n_in,
                              void* d_out, int out_size)
{
    const float* x    = (const float*)d_in[0];
    const float* sp   = (const float*)d_in[1];
    const float* sph  = (const float*)d_in[2];
    const float* bw1  = (const float*)d_in[3];
    const float* bb1  = (const float*)d_in[4];
    const float* bw2  = (const float*)d_in[5];
    const float* bb2  = (const float*)d_in[6];
    const float* bw3  = (const float*)d_in[7];
    const float* fw1  = (const float*)d_in[8];
    const float* fb1  = (const float*)d_in[9];
    const float* fw2  = (const float*)d_in[10];
    const float* fb2  = (const float*)d_in[11];
    const float* fw3  = (const float*)d_in[12];
    const float* bias = (const float*)d_in[13];

    weights_kernel<<<16, 128>>>(sp, sph, bw1, bb1, bw2, bb2, bw3,
                                fw1, fb1, fw2, fb2, fw3);

    dim3 gA(512, CH / 2, 2);
    conv_kernel<<<gA, 128>>>(x);

    mix_kernel<<<4096, 128>>>(bias, (float*)d_out);
}

// round 4
// speedup vs baseline: 1.1666x; 1.1144x over previous
#include <cuda_runtime.h>
#include <cuda_bf16.h>
#include <math.h>
#include <stdint.h>

#define NVEC 12
#define CIN  8
#define COUT 8
#define DIM  64
#define VOX  (DIM*DIM*DIM)      // 262144
#define CH   (CIN*NVEC)         // 96

// Device-global scratch (allocation-free per harness rules)
__device__ float g_sw[CH * 125];            // depthwise taps: [c][k]
__device__ float g_fwm[CH * CH];            // mixing matrix: [oc][fv]
__device__ float g_y[(size_t)2 * CH * VOX]; // depthwise conv output (192 MiB)

__device__ __forceinline__ float gelu_exact(float v) {
    return 0.5f * v * (1.0f + erff(v * 0.70710678118654752440f));
}

// ---------------------------------------------------------------------------
// Kernel W: tiny MLPs that generate the conv taps and the mixing matrix.
// ---------------------------------------------------------------------------
__global__ void weights_kernel(
    const float* __restrict__ sp, const float* __restrict__ sph,
    const float* __restrict__ bw1, const float* __restrict__ bb1,
    const float* __restrict__ bw2, const float* __restrict__ bb2,
    const float* __restrict__ bw3,
    const float* __restrict__ fw1, const float* __restrict__ fb1,
    const float* __restrict__ fw2, const float* __restrict__ fb2,
    const float* __restrict__ fw3)
{
    int tid0 = blockIdx.x * blockDim.x + threadIdx.x;
    int stride = gridDim.x * blockDim.x;

    for (int r = tid0; r < 1500; r += stride) {
        float s0 = sp[2 * r], s1 = sp[2 * r + 1];
        float a[14];
        a[0] = s0; a[1] = s1;
        a[2] = s0 * s0; a[3] = s0 * s1; a[4] = s1 * s0; a[5] = s1 * s1;
        #pragma unroll
        for (int i = 0; i < 4; i++) { a[6 + 2*i] = a[2 + i] * s0; a[7 + 2*i] = a[2 + i] * s1; }
        float h1[8], h2[8];
        #pragma unroll
        for (int j = 0; j < 8; j++) {
            float s = bb1[j];
            #pragma unroll
            for (int i = 0; i < 14; i++) s += bw1[j * 14 + i] * a[i];
            h1[j] = gelu_exact(s);
        }
        #pragma unroll
        for (int j = 0; j < 8; j++) {
            float s = bb2[j];
            #pragma unroll
            for (int i = 0; i < 8; i++) s += bw2[j * 8 + i] * h1[i];
            h2[j] = gelu_exact(s);
        }
        int k = r / 12, v = r % 12;
        #pragma unroll
        for (int f = 0; f < 8; f++) {
            float o = 0.f;
            #pragma unroll
            for (int i = 0; i < 8; i++) o += bw3[f * 8 + i] * h2[i];
            g_sw[(f * 12 + v) * 125 + k] = o;
        }
    }
    for (int r = tid0; r < 144; r += stride) {
        float c0 = sph[r];
        float a0 = c0, a1 = c0 * c0, a2 = c0 * c0 * c0;
        float h1[8], h2[8];
        #pragma unroll
        for (int j = 0; j < 8; j++) {
            float s = fb1[j] + fw1[j*3+0]*a0 + fw1[j*3+1]*a1 + fw1[j*3+2]*a2;
            h1[j] = gelu_exact(s);
        }
        #pragma unroll
        for (int j = 0; j < 8; j++) {
            float s = fb2[j];
            #pragma unroll
            for (int i = 0; i < 8; i++) s += fw2[j * 8 + i] * h1[i];
            h2[j] = gelu_exact(s);
        }
        int v = r / 12, w = r % 12;
        #pragma unroll
        for (int col = 0; col < 64; col++) {
            float o = 0.f;
            #pragma unroll
            for (int i = 0; i < 8; i++) o += fw3[col * 8 + i] * h2[i];
            int f = col >> 3, g = col & 7;
            g_fwm[(g * 12 + w) * CH + (f * 12 + v)] = o;   // [oc][fv]
        }
    }
}

// ---------------------------------------------------------------------------
// Kernel A: depthwise 5x5x5 conv (cross-correlation, SAME padding).
// Proven R1 structure: one block per (8^3 tile, channel, batch).
// ---------------------------------------------------------------------------
__global__ __launch_bounds__(128) void conv_kernel(const float* __restrict__ x)
{
    __shared__ __align__(16) float s_x[12 * 12 * 12];
    __shared__ __align__(16) float s_k[25 * 8];

    int tile = blockIdx.x;
    int c    = blockIdx.y;
    int b    = blockIdx.z;
    int tz = tile & 7, ty = (tile >> 3) & 7, tx = tile >> 6;
    int t = threadIdx.x;

    const float* xb = x + (size_t)(b * CH + c) * VOX;
    int gx0 = tx * 8 - 2, gy0 = ty * 8 - 2, gz0 = tz * 8 - 2;

    for (int i = t; i < 1728; i += 128) {
        int lx = i / 144, rr = i % 144, ly = rr / 12, lz = rr % 12;
        int gx = gx0 + lx, gy = gy0 + ly, gz = gz0 + lz;
        float vv = 0.f;
        if ((unsigned)gx < 64u && (unsigned)gy < 64u && (unsigned)gz < 64u)
            vv = xb[(gx << 12) + (gy << 6) + gz];
        s_x[i] = vv;
    }
    if (t < 125) {
        int kx = t / 25, rr = t % 25, ky = rr / 5, kz = rr % 5;
        s_k[(kx * 5 + ky) * 8 + kz] = g_sw[c * 125 + t];
    }
    __syncthreads();

    int ox = t >> 4;
    int oy = (t >> 1) & 7;
    int z0 = (t & 1) * 4;

    float a0 = 0.f, a1 = 0.f, a2 = 0.f, a3 = 0.f;
    #pragma unroll
    for (int kx = 0; kx < 5; kx++) {
        #pragma unroll
        for (int ky = 0; ky < 5; ky++) {
            const float* xp = &s_x[((ox + kx) * 12 + (oy + ky)) * 12 + z0];
            float4 va = *(const float4*)xp;
            float4 vb = *(const float4*)(xp + 4);
            float xs0 = va.x, xs1 = va.y, xs2 = va.z, xs3 = va.w;
            float xs4 = vb.x, xs5 = vb.y, xs6 = vb.z, xs7 = vb.w;
            const float* kp = &s_k[(kx * 5 + ky) * 8];
            float4 tt = *(const float4*)kp;
            float t4 = kp[4];
            a0 += xs0*tt.x + xs1*tt.y + xs2*tt.z + xs3*tt.w + xs4*t4;
            a1 += xs1*tt.x + xs2*tt.y + xs3*tt.z + xs4*tt.w + xs5*t4;
            a2 += xs2*tt.x + xs3*tt.y + xs4*tt.z + xs5*tt.w + xs6*t4;
            a3 += xs3*tt.x + xs4*tt.y + xs5*tt.z + xs6*tt.w + xs7*t4;
        }
    }
    size_t oidx = (size_t)(b * CH + c) * VOX
                + (size_t)((tx * 8 + ox) << 12) + ((ty * 8 + oy) << 6) + tz * 8 + z0;
    *(float4*)&g_y[oidx] = make_float4(a0, a1, a2, a3);
}

// ---------------------------------------------------------------------------
// Kernel B: per-voxel 96x96 channel mixing on mma.sync bf16 tensor cores.
// D[128 vox, 96 oc] = Y[128 vox, 96 fv] @ W[96 oc, 96 fv]^T
// bf16 hi/lo split, 3 passes (Ah*Bh + Al*Bh + Ah*Bl), fp32 accum.
// mma.m16n8k16 fragments built with direct LDS.32 per the PTX fragment map.
// ---------------------------------------------------------------------------
#define PA 106   // A smem pitch (bf16 elems), conflict-free frag reads
#define PB 102   // B smem pitch (bf16 elems)
#define PD 130   // D staging pitch (floats)

#define OFF_AH 0
#define OFF_AL 27136                 // 128*106*2
#define OFF_BH 54272
#define OFF_BL 73856                 // + 96*102*2
#define MIX_SMEM_TOTAL 93440         // + 96*102*2

__device__ __forceinline__ void mma16816(float* c, const uint32_t a[4],
                                         uint32_t b0, uint32_t b1) {
    asm volatile(
        "mma.sync.aligned.m16n8k16.row.col.f32.bf16.bf16.f32 "
        "{%0,%1,%2,%3}, {%4,%5,%6,%7}, {%8,%9}, {%0,%1,%2,%3};"
        : "+f"(c[0]), "+f"(c[1]), "+f"(c[2]), "+f"(c[3])
        : "r"(a[0]), "r"(a[1]), "r"(a[2]), "r"(a[3]), "r"(b0), "r"(b1));
}

// split float into truncated-bf16 hi pair + rounded-bf16 lo pair (packed u32)
__device__ __forceinline__ void split2(float y0, float y1, uint32_t& hi, uint32_t& lo) {
    uint32_t u0 = __float_as_uint(y0), u1 = __float_as_uint(y1);
    float h0 = __uint_as_float(u0 & 0xFFFF0000u);
    float h1 = __uint_as_float(u1 & 0xFFFF0000u);
    hi = __byte_perm(u0, u1, 0x7632);                     // {bf16(y0) lo, bf16(y1) hi}
    asm("cvt.rn.bf16x2.f32 %0, %1, %2;" : "=r"(lo) : "f"(y1 - h1), "f"(y0 - h0));
}

__global__ __launch_bounds__(128) void mix_kernel(
    const float* __restrict__ bias, float* __restrict__ out)
{
    extern __shared__ __align__(16) char smem[];
    uint16_t* Ah = (uint16_t*)(smem + OFF_AH);
    uint16_t* Al = (uint16_t*)(smem + OFF_AL);
    uint16_t* Bh = (uint16_t*)(smem + OFF_BH);
    uint16_t* Bl = (uint16_t*)(smem + OFF_BL);

    int t    = threadIdx.x;
    int wid  = t >> 5;
    int lane = t & 31;
    int g    = lane >> 2;      // group row
    int q    = lane & 3;       // thread in group

    int tv = blockIdx.x;               // 0..4095
    int b  = tv >> 11;
    int p0 = (tv & 2047) * 128;

    // ---- stage W (hi/lo bf16) ----
    for (int idx = t; idx < CH * 48; idx += 128) {
        int oc = idx / 48, j = idx % 48;          // fv pair (2j, 2j+1)
        float w0 = g_fwm[oc * CH + 2 * j];
        float w1 = g_fwm[oc * CH + 2 * j + 1];
        uint32_t hi, lo;
        split2(w0, w1, hi, lo);
        *(uint32_t*)(Bh + oc * PB + 2 * j) = hi;
        *(uint32_t*)(Bl + oc * PB + 2 * j) = lo;
    }

    // ---- stage Y tile (hi/lo bf16): row = voxel (this thread), col = ch ----
    {
        const float* yb = g_y + (size_t)b * CH * VOX + p0 + t;
        #pragma unroll 8
        for (int cp = 0; cp < 48; cp++) {
            float y0 = yb[(size_t)(2 * cp) * VOX];
            float y1 = yb[(size_t)(2 * cp + 1) * VOX];
            uint32_t hi, lo;
            split2(y0, y1, hi, lo);
            *(uint32_t*)(Ah + t * PA + 2 * cp) = hi;
            *(uint32_t*)(Al + t * PA + 2 * cp) = lo;
        }
    }
    __syncthreads();

    // ---- MMA: each warp computes 32 voxels x 96 oc ----
    int m0 = wid * 32;
    float acc[2][12][4];
    #pragma unroll
    for (int mt = 0; mt < 2; mt++)
        #pragma unroll
        for (int n = 0; n < 12; n++)
            #pragma unroll
            for (int i = 0; i < 4; i++) acc[mt][n][i] = 0.f;

    const uint16_t* Asrc[3] = { Ah, Al, Ah };
    const uint16_t* Bsrc[3] = { Bh, Bh, Bl };
    #pragma unroll 1
    for (int pass = 0; pass < 3; pass++) {
        const uint16_t* As = Asrc[pass];
        const uint16_t* Bs = Bsrc[pass];
        #pragma unroll
        for (int k = 0; k < 6; k++) {
            int k0 = k * 16;
            uint32_t af[2][4];
            #pragma unroll
            for (int mt = 0; mt < 2; mt++) {
                const uint16_t* p1 = As + (m0 + mt * 16 + g) * PA + k0 + q * 2;
                const uint16_t* p2 = p1 + 8 * PA;
                af[mt][0] = *(const uint32_t*)p1;
                af[mt][1] = *(const uint32_t*)p2;
                af[mt][2] = *(const uint32_t*)(p1 + 8);
                af[mt][3] = *(const uint32_t*)(p2 + 8);
            }
            #pragma unroll
            for (int n = 0; n < 12; n++) {
                const uint16_t* pb = Bs + (n * 8 + g) * PB + k0 + q * 2;
                uint32_t b0 = *(const uint32_t*)pb;
                uint32_t b1 = *(const uint32_t*)(pb + 8);
                mma16816(acc[0][n], af[0], b0, b1);
                mma16816(acc[1][n], af[1], b0, b1);
            }
        }
    }

    // ---- stage D to smem (reuse A region), then coalesced writeback ----
    __syncthreads();
    float* D = (float*)(smem + OFF_AH);
    #pragma unroll
    for (int mt = 0; mt < 2; mt++) {
        int r1 = m0 + mt * 16 + g;
        #pragma unroll
        for (int n = 0; n < 12; n++) {
            int ocb = n * 8 + 2 * q;
            D[(ocb)     * PD + r1]     = acc[mt][n][0];
            D[(ocb + 1) * PD + r1]     = acc[mt][n][1];
            D[(ocb)     * PD + r1 + 8] = acc[mt][n][2];
            D[(ocb + 1) * PD + r1 + 8] = acc[mt][n][3];
        }
    }
    __syncthreads();

    float bv[8];
    #pragma unroll
    for (int i = 0; i < 8; i++) bv[i] = bias[i];
    float* ob = out + (size_t)b * CH * VOX + p0 + t;
    #pragma unroll
    for (int c = 0; c < CH; c++)
        ob[(size_t)c * VOX] = D[c * PD + t] + bv[c / 12];
}

// ---------------------------------------------------------------------------
extern "C" void kernel_launch(void* const* d_in, const int* in_sizes, int n_in,
                              void* d_out, int out_size)
{
    const float* x    = (const float*)d_in[0];
    const float* sp   = (const float*)d_in[1];
    const float* sph  = (const float*)d_in[2];
    const float* bw1  = (const float*)d_in[3];
    const float* bb1  = (const float*)d_in[4];
    const float* bw2  = (const float*)d_in[5];
    const float* bb2  = (const float*)d_in[6];
    const float* bw3  = (const float*)d_in[7];
    const float* fw1  = (const float*)d_in[8];
    const float* fb1  = (const float*)d_in[9];
    const float* fw2  = (const float*)d_in[10];
    const float* fb2  = (const float*)d_in[11];
    const float* fw3  = (const float*)d_in[12];
    const float* bias = (const float*)d_in[13];

    cudaFuncSetAttribute(mix_kernel, cudaFuncAttributeMaxDynamicSharedMemorySize,
                         MIX_SMEM_TOTAL);

    weights_kernel<<<16, 128>>>(sp, sph, bw1, bb1, bw2, bb2, bw3,
                                fw1, fb1, fw2, fb2, fw3);

    dim3 gA(512, CH, 2);
    conv_kernel<<<gA, 128>>>(x);

    mix_kernel<<<4096, 128, MIX_SMEM_TOTAL>>>(bias, (float*)d_out);
}

// round 5
// speedup vs baseline: 1.4912x; 1.2782x over previous
#include <cuda_runtime.h>
#include <cuda_bf16.h>
#include <math.h>
#include <stdint.h>

#define NVEC 12
#define CIN  8
#define COUT 8
#define DIM  64
#define VOX  (DIM*DIM*DIM)      // 262144
#define CH   (CIN*NVEC)         // 96

// Device-global scratch (allocation-free per harness rules)
__device__ float g_fwm[CH * CH];            // mixing matrix: [oc][fv]
__device__ float g_y[(size_t)2 * CH * VOX]; // depthwise conv output (192 MiB)

__device__ __forceinline__ float gelu_exact(float v) {
    return 0.5f * v * (1.0f + erff(v * 0.70710678118654752440f));
}

// ---------------------------------------------------------------------------
// Kernel A: depthwise 5x5x5 conv (cross-correlation, SAME padding).
// 8x8x32 tiles, 256 threads, one full 8-z column per thread.
// Taps for this block's channel generated inline by a tiny MLP (125 threads).
// Block (0,0,0) additionally generates the mixing matrix g_fwm.
// ---------------------------------------------------------------------------
__global__ __launch_bounds__(256) void conv_kernel(
    const float* __restrict__ x,
    const float* __restrict__ sp,   // [1500,2]
    const float* __restrict__ sph,  // [144,1]
    const float* __restrict__ bw1, const float* __restrict__ bb1,
    const float* __restrict__ bw2, const float* __restrict__ bb2,
    const float* __restrict__ bw3,
    const float* __restrict__ fw1, const float* __restrict__ fb1,
    const float* __restrict__ fw2, const float* __restrict__ fb2,
    const float* __restrict__ fw3)
{
    __shared__ __align__(16) float s_x[12 * 12 * 36];   // pitch-36 z rows
    __shared__ __align__(16) float s_k[25 * 8];         // taps, 8/pos padded

    int tile = blockIdx.x;            // 0..127
    int c    = blockIdx.y;            // 0..95
    int b    = blockIdx.z;            // 0..1
    int tx = tile >> 4, ty = (tile >> 1) & 7, tz = tile & 1;
    int t = threadIdx.x;

    // ---- inline tap MLP: basis(spatial_attr[k*12+v]) -> tap[k] for f=c/12 ----
    if (t < 125) {
        int v = c % 12, f = c / 12;
        int r = t * 12 + v;
        float s0 = sp[2 * r], s1 = sp[2 * r + 1];
        float a[14];
        a[0] = s0; a[1] = s1;
        a[2] = s0 * s0; a[3] = s0 * s1; a[4] = s1 * s0; a[5] = s1 * s1;
        #pragma unroll
        for (int i = 0; i < 4; i++) { a[6 + 2*i] = a[2 + i] * s0; a[7 + 2*i] = a[2 + i] * s1; }
        float h1[8], h2[8];
        #pragma unroll
        for (int j = 0; j < 8; j++) {
            float s = bb1[j];
            #pragma unroll
            for (int i = 0; i < 14; i++) s += bw1[j * 14 + i] * a[i];
            h1[j] = gelu_exact(s);
        }
        #pragma unroll
        for (int j = 0; j < 8; j++) {
            float s = bb2[j];
            #pragma unroll
            for (int i = 0; i < 8; i++) s += bw2[j * 8 + i] * h1[i];
            h2[j] = gelu_exact(s);
        }
        float o = 0.f;
        #pragma unroll
        for (int i = 0; i < 8; i++) o += bw3[f * 8 + i] * h2[i];
        int kx = t / 25, rr = t % 25, ky = rr / 5, kz = rr % 5;
        s_k[(kx * 5 + ky) * 8 + kz] = o;
    }

    // ---- halo load: 12 x 12 x 36 ----
    const float* xb = x + (size_t)(b * CH + c) * VOX;
    int gx0 = tx * 8 - 2, gy0 = ty * 8 - 2, gz0 = tz * 32 - 2;
    for (int i = t; i < 5184; i += 256) {
        int lx = i / 432, r = i % 432, ly = r / 36, lz = r % 36;
        int gx = gx0 + lx, gy = gy0 + ly, gz = gz0 + lz;
        float vv = 0.f;
        if ((unsigned)gx < 64u && (unsigned)gy < 64u && (unsigned)gz < 64u)
            vv = xb[(gx << 12) + (gy << 6) + gz];
        s_x[i] = vv;
    }
    __syncthreads();

    int xy = t >> 2;
    int ox = xy >> 3, oy = xy & 7;
    int zo = (t & 3) * 8;

    float acc0 = 0.f, acc1 = 0.f, acc2 = 0.f, acc3 = 0.f;
    float acc4 = 0.f, acc5 = 0.f, acc6 = 0.f, acc7 = 0.f;
    #pragma unroll
    for (int kx = 0; kx < 5; kx++) {
        #pragma unroll
        for (int ky = 0; ky < 5; ky++) {
            const float* xp = &s_x[((ox + kx) * 12 + (oy + ky)) * 36 + zo];
            float4 vA = *(const float4*)xp;
            float4 vB = *(const float4*)(xp + 4);
            float4 vC = *(const float4*)(xp + 8);
            float f0 = vA.x, f1 = vA.y, f2 = vA.z, f3 = vA.w;
            float f4 = vB.x, f5 = vB.y, f6 = vB.z, f7 = vB.w;
            float f8 = vC.x, f9 = vC.y, f10 = vC.z, f11 = vC.w;
            const float* kp = &s_k[(kx * 5 + ky) * 8];
            float4 tv = *(const float4*)kp;
            float t4 = kp[4];
            acc0 += f0*tv.x + f1*tv.y + f2*tv.z + f3*tv.w + f4*t4;
            acc1 += f1*tv.x + f2*tv.y + f3*tv.z + f4*tv.w + f5*t4;
            acc2 += f2*tv.x + f3*tv.y + f4*tv.z + f5*tv.w + f6*t4;
            acc3 += f3*tv.x + f4*tv.y + f5*tv.z + f6*tv.w + f7*t4;
            acc4 += f4*tv.x + f5*tv.y + f6*tv.z + f7*tv.w + f8*t4;
            acc5 += f5*tv.x + f6*tv.y + f7*tv.z + f8*tv.w + f9*t4;
            acc6 += f6*tv.x + f7*tv.y + f8*tv.z + f9*tv.w + f10*t4;
            acc7 += f7*tv.x + f8*tv.y + f9*tv.z + f10*tv.w + f11*t4;
        }
    }
    size_t oidx = (size_t)(b * CH + c) * VOX
                + (size_t)((tx * 8 + ox) << 12) + ((ty * 8 + oy) << 6) + tz * 32 + zo;
    *(float4*)&g_y[oidx]     = make_float4(acc0, acc1, acc2, acc3);
    *(float4*)&g_y[oidx + 4] = make_float4(acc4, acc5, acc6, acc7);

    // ---- block (0,0,0): generate mixing matrix (mix kernel runs after) ----
    if (blockIdx.x == 0 && c == 0 && b == 0 && t < 144) {
        int r = t;
        float c0 = sph[r];
        float a0 = c0, a1 = c0 * c0, a2 = c0 * c0 * c0;
        float h1[8], h2[8];
        #pragma unroll
        for (int j = 0; j < 8; j++) {
            float s = fb1[j] + fw1[j*3+0]*a0 + fw1[j*3+1]*a1 + fw1[j*3+2]*a2;
            h1[j] = gelu_exact(s);
        }
        #pragma unroll
        for (int j = 0; j < 8; j++) {
            float s = fb2[j];
            #pragma unroll
            for (int i = 0; i < 8; i++) s += fw2[j * 8 + i] * h1[i];
            h2[j] = gelu_exact(s);
        }
        int v = r / 12, w = r % 12;
        #pragma unroll
        for (int col = 0; col < 64; col++) {
            float o = 0.f;
            #pragma unroll
            for (int i = 0; i < 8; i++) o += fw3[col * 8 + i] * h2[i];
            int f = col >> 3, g = col & 7;
            g_fwm[(g * 12 + w) * CH + (f * 12 + v)] = o;   // [oc][fv]
        }
    }
}

// ---------------------------------------------------------------------------
// Kernel B: per-voxel 96x96 channel mixing on mma.sync bf16 tensor cores.
// D[128 vox, 96 oc] = Y[128 vox, 96 fv] @ W[96 oc, 96 fv]^T
// bf16 hi/lo split, 3 passes (Ah*Bh + Al*Bh + Ah*Bl), fp32 accum.
// Conflict-free smem: pitch 104 (52 u32) + XOR swizzle on A staging cols.
// ---------------------------------------------------------------------------
#define PA32 52     // A pitch in u32 (104 bf16)
#define PB32 52     // B pitch in u32
#define PD   132    // D staging pitch (floats)

#define OFF_AH 0
#define OFF_AL 26624                 // 128*52*4
#define OFF_BH 53248
#define OFF_BL 73216                 // + 96*52*4
#define MIX_SMEM_TOTAL 93184         // + 96*52*4

__device__ __forceinline__ void mma16816(float* c, const uint32_t a[4],
                                         uint32_t b0, uint32_t b1) {
    asm volatile(
        "mma.sync.aligned.m16n8k16.row.col.f32.bf16.bf16.f32 "
        "{%0,%1,%2,%3}, {%4,%5,%6,%7}, {%8,%9}, {%0,%1,%2,%3};"
        : "+f"(c[0]), "+f"(c[1]), "+f"(c[2]), "+f"(c[3])
        : "r"(a[0]), "r"(a[1]), "r"(a[2]), "r"(a[3]), "r"(b0), "r"(b1));
}

// split float pair into truncated-bf16 hi pair + rounded-bf16 lo pair
__device__ __forceinline__ void split2(float y0, float y1, uint32_t& hi, uint32_t& lo) {
    uint32_t u0 = __float_as_uint(y0), u1 = __float_as_uint(y1);
    float h0 = __uint_as_float(u0 & 0xFFFF0000u);
    float h1 = __uint_as_float(u1 & 0xFFFF0000u);
    hi = __byte_perm(u0, u1, 0x7632);
    asm("cvt.rn.bf16x2.f32 %0, %1, %2;" : "=r"(lo) : "f"(y1 - h1), "f"(y0 - h0));
}

__global__ __launch_bounds__(128) void mix_kernel(
    const float* __restrict__ bias, float* __restrict__ out)
{
    extern __shared__ __align__(16) char smem[];
    uint32_t* Ah = (uint32_t*)(smem + OFF_AH);
    uint32_t* Al = (uint32_t*)(smem + OFF_AL);
    uint32_t* Bh = (uint32_t*)(smem + OFF_BH);
    uint32_t* Bl = (uint32_t*)(smem + OFF_BL);

    int t    = threadIdx.x;
    int wid  = t >> 5;
    int lane = t & 31;
    int g    = lane >> 2;      // group row
    int q    = lane & 3;       // thread in group

    int tv = blockIdx.x;               // 0..4095
    int b  = tv >> 11;
    int p0 = (tv & 2047) * 128;

    // ---- stage W (hi/lo bf16): row oc, u32 col j = fv pair ----
    for (int idx = t; idx < CH * 48; idx += 128) {
        int oc = idx / 48, j = idx % 48;
        float w0 = g_fwm[oc * CH + 2 * j];
        float w1 = g_fwm[oc * CH + 2 * j + 1];
        uint32_t hi, lo;
        split2(w0, w1, hi, lo);
        Bh[oc * PB32 + j] = hi;
        Bl[oc * PB32 + j] = lo;
    }

    // ---- stage Y tile (hi/lo bf16) with XOR-swizzled columns ----
    {
        const float* yb = g_y + (size_t)b * CH * VOX + p0 + t;
        int sw = (t >> 3) & 3;
        #pragma unroll 8
        for (int cp = 0; cp < 48; cp++) {
            float y0 = yb[(size_t)(2 * cp) * VOX];
            float y1 = yb[(size_t)(2 * cp + 1) * VOX];
            uint32_t hi, lo;
            split2(y0, y1, hi, lo);
            Ah[t * PA32 + (cp ^ sw)] = hi;
            Al[t * PA32 + (cp ^ sw)] = lo;
        }
    }
    __syncthreads();

    // ---- MMA: each warp computes 32 voxels x 96 oc ----
    int m0 = wid * 32;
    float acc[2][12][4];
    #pragma unroll
    for (int mt = 0; mt < 2; mt++)
        #pragma unroll
        for (int n = 0; n < 12; n++)
            #pragma unroll
            for (int i = 0; i < 4; i++) acc[mt][n][i] = 0.f;

    const uint32_t* Asrc[3] = { Ah, Al, Ah };
    const uint32_t* Bsrc[3] = { Bh, Bh, Bl };
    #pragma unroll 1
    for (int pass = 0; pass < 3; pass++) {
        const uint32_t* As = Asrc[pass];
        const uint32_t* Bs = Bsrc[pass];
        #pragma unroll
        for (int k = 0; k < 6; k++) {
            int c0 = 8 * k + q;
            uint32_t af[2][4];
            #pragma unroll
            for (int mt = 0; mt < 2; mt++) {
                int row0 = m0 + mt * 16 + g;
                int s0 = 2 * mt, s1 = 2 * mt + 1;
                af[mt][0] = As[row0 * PA32       + (c0 ^ s0)];
                af[mt][1] = As[(row0 + 8) * PA32 + (c0 ^ s1)];
                af[mt][2] = As[row0 * PA32       + ((c0 + 4) ^ s0)];
                af[mt][3] = As[(row0 + 8) * PA32 + ((c0 + 4) ^ s1)];
            }
            #pragma unroll
            for (int n = 0; n < 12; n++) {
                const uint32_t* pb = Bs + (n * 8 + g) * PB32 + 8 * k + q;
                uint32_t b0 = pb[0];
                uint32_t b1 = pb[4];
                mma16816(acc[0][n], af[0], b0, b1);
                mma16816(acc[1][n], af[1], b0, b1);
            }
        }
    }

    // ---- stage D to smem (reuse A region), then coalesced writeback ----
    __syncthreads();
    float* D = (float*)(smem + OFF_AH);
    #pragma unroll
    for (int mt = 0; mt < 2; mt++) {
        int r1 = m0 + mt * 16 + g;
        #pragma unroll
        for (int n = 0; n < 12; n++) {
            int ocb = n * 8 + 2 * q;
            D[(ocb)     * PD + r1]     = acc[mt][n][0];
            D[(ocb + 1) * PD + r1]     = acc[mt][n][1];
            D[(ocb)     * PD + r1 + 8] = acc[mt][n][2];
            D[(ocb + 1) * PD + r1 + 8] = acc[mt][n][3];
        }
    }
    __syncthreads();

    float bv[8];
    #pragma unroll
    for (int i = 0; i < 8; i++) bv[i] = bias[i];
    float* ob = out + (size_t)b * CH * VOX + p0 + t;
    #pragma unroll
    for (int c = 0; c < CH; c++)
        ob[(size_t)c * VOX] = D[c * PD + t] + bv[c / 12];
}

// ---------------------------------------------------------------------------
extern "C" void kernel_launch(void* const* d_in, const int* in_sizes, int n_in,
                              void* d_out, int out_size)
{
    const float* x    = (const float*)d_in[0];
    const float* sp   = (const float*)d_in[1];
    const float* sph  = (const float*)d_in[2];
    const float* bw1  = (const float*)d_in[3];
    const float* bb1  = (const float*)d_in[4];
    const float* bw2  = (const float*)d_in[5];
    const float* bb2  = (const float*)d_in[6];
    const float* bw3  = (const float*)d_in[7];
    const float* fw1  = (const float*)d_in[8];
    const float* fb1  = (const float*)d_in[9];
    const float* fw2  = (const float*)d_in[10];
    const float* fb2  = (const float*)d_in[11];
    const float* fw3  = (const float*)d_in[12];
    const float* bias = (const float*)d_in[13];

    cudaFuncSetAttribute(mix_kernel, cudaFuncAttributeMaxDynamicSharedMemorySize,
                         MIX_SMEM_TOTAL);

    dim3 gA(128, CH, 2);
    conv_kernel<<<gA, 256>>>(x, sp, sph, bw1, bb1, bw2, bb2, bw3,
                             fw1, fb1, fw2, fb2, fw3);

    mix_kernel<<<4096, 128, MIX_SMEM_TOTAL>>>(bias, (float*)d_out);
}

// round 6
// speedup vs baseline: 1.7463x; 1.1711x over previous
#include <cuda_runtime.h>
#include <cuda_bf16.h>
#include <math.h>
#include <stdint.h>

#define NVEC 12
#define CIN  8
#define COUT 8
#define DIM  64
#define VOX  (DIM*DIM*DIM)      // 262144
#define CH   (CIN*NVEC)         // 96

// Device-global scratch (allocation-free per harness rules)
__device__ float g_sw[CH * 125];            // depthwise taps: [c][k]
__device__ float g_fwm[CH * CH];            // mixing matrix: [oc][fv]
__device__ float g_y[(size_t)2 * CH * VOX]; // depthwise conv output (192 MiB)

__device__ __forceinline__ float gelu_exact(float v) {
    return 0.5f * v * (1.0f + erff(v * 0.70710678118654752440f));
}

// ---------------------------------------------------------------------------
// Kernel W (light): 1 thread per attr row. 1500 spatial rows (each -> 8 taps),
// 144 fiber rows (each -> 64 mixing entries). grid 13 x 128 = 1664 threads.
// ---------------------------------------------------------------------------
__global__ __launch_bounds__(128) void weights_kernel(
    const float* __restrict__ sp, const float* __restrict__ sph,
    const float* __restrict__ bw1, const float* __restrict__ bb1,
    const float* __restrict__ bw2, const float* __restrict__ bb2,
    const float* __restrict__ bw3,
    const float* __restrict__ fw1, const float* __restrict__ fb1,
    const float* __restrict__ fw2, const float* __restrict__ fb2,
    const float* __restrict__ fw3)
{
    int tid = blockIdx.x * blockDim.x + threadIdx.x;

    if (tid < 1500) {
        int r = tid;
        float s0 = sp[2 * r], s1 = sp[2 * r + 1];
        float a[14];
        a[0] = s0; a[1] = s1;
        a[2] = s0 * s0; a[3] = s0 * s1; a[4] = s1 * s0; a[5] = s1 * s1;
        #pragma unroll
        for (int i = 0; i < 4; i++) { a[6 + 2*i] = a[2 + i] * s0; a[7 + 2*i] = a[2 + i] * s1; }
        float h1[8], h2[8];
        #pragma unroll
        for (int j = 0; j < 8; j++) {
            float s = bb1[j];
            #pragma unroll
            for (int i = 0; i < 14; i++) s += bw1[j * 14 + i] * a[i];
            h1[j] = gelu_exact(s);
        }
        #pragma unroll
        for (int j = 0; j < 8; j++) {
            float s = bb2[j];
            #pragma unroll
            for (int i = 0; i < 8; i++) s += bw2[j * 8 + i] * h1[i];
            h2[j] = gelu_exact(s);
        }
        int k = r / 12, v = r % 12;
        #pragma unroll
        for (int f = 0; f < 8; f++) {
            float o = 0.f;
            #pragma unroll
            for (int i = 0; i < 8; i++) o += bw3[f * 8 + i] * h2[i];
            g_sw[(f * 12 + v) * 125 + k] = o;
        }
    } else if (tid < 1644) {
        int r = tid - 1500;
        float c0 = sph[r];
        float a0 = c0, a1 = c0 * c0, a2 = c0 * c0 * c0;
        float h1[8], h2[8];
        #pragma unroll
        for (int j = 0; j < 8; j++) {
            float s = fb1[j] + fw1[j*3+0]*a0 + fw1[j*3+1]*a1 + fw1[j*3+2]*a2;
            h1[j] = gelu_exact(s);
        }
        #pragma unroll
        for (int j = 0; j < 8; j++) {
            float s = fb2[j];
            #pragma unroll
            for (int i = 0; i < 8; i++) s += fw2[j * 8 + i] * h1[i];
            h2[j] = gelu_exact(s);
        }
        int v = r / 12, w = r % 12;
        #pragma unroll
        for (int col = 0; col < 64; col++) {
            float o = 0.f;
            #pragma unroll
            for (int i = 0; i < 8; i++) o += fw3[col * 8 + i] * h2[i];
            int f = col >> 3, g = col & 7;
            g_fwm[(g * 12 + w) * CH + (f * 12 + v)] = o;   // [oc][fv]
        }
    }
}

// ---------------------------------------------------------------------------
// Kernel A: depthwise 5x5x5 conv (cross-correlation, SAME padding).
// 8x8x32 tiles, 256 threads, one full 8-z column per thread.
// ---------------------------------------------------------------------------
__global__ __launch_bounds__(256) void conv_kernel(const float* __restrict__ x)
{
    __shared__ __align__(16) float s_x[12 * 12 * 36];   // pitch-36 z rows
    __shared__ __align__(16) float s_k[25 * 8];         // taps, 8/pos padded

    int tile = blockIdx.x;            // 0..127
    int c    = blockIdx.y;            // 0..95
    int b    = blockIdx.z;            // 0..1
    int tx = tile >> 4, ty = (tile >> 1) & 7, tz = tile & 1;
    int t = threadIdx.x;

    if (t < 125) {
        int kx = t / 25, rr = t % 25, ky = rr / 5, kz = rr % 5;
        s_k[(kx * 5 + ky) * 8 + kz] = g_sw[c * 125 + t];
    }

    // ---- halo load: 12 x 12 x 36 ----
    const float* xb = x + (size_t)(b * CH + c) * VOX;
    int gx0 = tx * 8 - 2, gy0 = ty * 8 - 2, gz0 = tz * 32 - 2;
    for (int i = t; i < 5184; i += 256) {
        int lx = i / 432, r = i % 432, ly = r / 36, lz = r % 36;
        int gx = gx0 + lx, gy = gy0 + ly, gz = gz0 + lz;
        float vv = 0.f;
        if ((unsigned)gx < 64u && (unsigned)gy < 64u && (unsigned)gz < 64u)
            vv = xb[(gx << 12) + (gy << 6) + gz];
        s_x[i] = vv;
    }
    __syncthreads();

    int xy = t >> 2;
    int ox = xy >> 3, oy = xy & 7;
    int zo = (t & 3) * 8;

    float acc0 = 0.f, acc1 = 0.f, acc2 = 0.f, acc3 = 0.f;
    float acc4 = 0.f, acc5 = 0.f, acc6 = 0.f, acc7 = 0.f;
    #pragma unroll
    for (int kx = 0; kx < 5; kx++) {
        #pragma unroll
        for (int ky = 0; ky < 5; ky++) {
            const float* xp = &s_x[((ox + kx) * 12 + (oy + ky)) * 36 + zo];
            float4 vA = *(const float4*)xp;
            float4 vB = *(const float4*)(xp + 4);
            float4 vC = *(const float4*)(xp + 8);
            float f0 = vA.x, f1 = vA.y, f2 = vA.z, f3 = vA.w;
            float f4 = vB.x, f5 = vB.y, f6 = vB.z, f7 = vB.w;
            float f8 = vC.x, f9 = vC.y, f10 = vC.z, f11 = vC.w;
            const float* kp = &s_k[(kx * 5 + ky) * 8];
            float4 tv = *(const float4*)kp;
            float t4 = kp[4];
            acc0 += f0*tv.x + f1*tv.y + f2*tv.z + f3*tv.w + f4*t4;
            acc1 += f1*tv.x + f2*tv.y + f3*tv.z + f4*tv.w + f5*t4;
            acc2 += f2*tv.x + f3*tv.y + f4*tv.z + f5*tv.w + f6*t4;
            acc3 += f3*tv.x + f4*tv.y + f5*tv.z + f6*tv.w + f7*t4;
            acc4 += f4*tv.x + f5*tv.y + f6*tv.z + f7*tv.w + f8*t4;
            acc5 += f5*tv.x + f6*tv.y + f7*tv.z + f8*tv.w + f9*t4;
            acc6 += f6*tv.x + f7*tv.y + f8*tv.z + f9*tv.w + f10*t4;
            acc7 += f7*tv.x + f8*tv.y + f9*tv.z + f10*tv.w + f11*t4;
        }
    }
    size_t oidx = (size_t)(b * CH + c) * VOX
                + (size_t)((tx * 8 + ox) << 12) + ((ty * 8 + oy) << 6) + tz * 32 + zo;
    *(float4*)&g_y[oidx]     = make_float4(acc0, acc1, acc2, acc3);
    *(float4*)&g_y[oidx + 4] = make_float4(acc4, acc5, acc6, acc7);
}

// ---------------------------------------------------------------------------
// Kernel B: per-voxel 96x96 channel mixing on mma.sync bf16 tensor cores.
// D[128 vox, 96 oc] = Y[128 vox, 96 fv] @ W[96 oc, 96 fv]^T
// bf16 hi/lo split, 3 passes (Ah*Bh + Al*Bh + Ah*Bl), fp32 accum.
// 4 voxel tiles per block; W staged once per block.
// ---------------------------------------------------------------------------
#define PA32 52     // A pitch in u32 (104 bf16)
#define PB32 52     // B pitch in u32
#define PD   132    // D staging pitch (floats)

#define OFF_AH 0
#define OFF_AL 26624                 // 128*52*4
#define OFF_BH 53248
#define OFF_BL 73216                 // + 96*52*4
#define MIX_SMEM_TOTAL 93184         // + 96*52*4

#define MIX_TILES 4

__device__ __forceinline__ void mma16816(float* c, const uint32_t a[4],
                                         uint32_t b0, uint32_t b1) {
    asm volatile(
        "mma.sync.aligned.m16n8k16.row.col.f32.bf16.bf16.f32 "
        "{%0,%1,%2,%3}, {%4,%5,%6,%7}, {%8,%9}, {%0,%1,%2,%3};"
        : "+f"(c[0]), "+f"(c[1]), "+f"(c[2]), "+f"(c[3])
        : "r"(a[0]), "r"(a[1]), "r"(a[2]), "r"(a[3]), "r"(b0), "r"(b1));
}

// split float pair into truncated-bf16 hi pair + rounded-bf16 lo pair
__device__ __forceinline__ void split2(float y0, float y1, uint32_t& hi, uint32_t& lo) {
    uint32_t u0 = __float_as_uint(y0), u1 = __float_as_uint(y1);
    float h0 = __uint_as_float(u0 & 0xFFFF0000u);
    float h1 = __uint_as_float(u1 & 0xFFFF0000u);
    hi = __byte_perm(u0, u1, 0x7632);
    asm("cvt.rn.bf16x2.f32 %0, %1, %2;" : "=r"(lo) : "f"(y1 - h1), "f"(y0 - h0));
}

__global__ __launch_bounds__(128) void mix_kernel(
    const float* __restrict__ bias, float* __restrict__ out)
{
    extern __shared__ __align__(16) char smem[];
    uint32_t* Ah = (uint32_t*)(smem + OFF_AH);
    uint32_t* Al = (uint32_t*)(smem + OFF_AL);
    uint32_t* Bh = (uint32_t*)(smem + OFF_BH);
    uint32_t* Bl = (uint32_t*)(smem + OFF_BL);

    int t    = threadIdx.x;
    int wid  = t >> 5;
    int lane = t & 31;
    int g    = lane >> 2;      // group row
    int q    = lane & 3;       // thread in group

    // ---- stage W (hi/lo bf16) once per block ----
    for (int idx = t; idx < CH * 48; idx += 128) {
        int oc = idx / 48, j = idx % 48;
        float w0 = g_fwm[oc * CH + 2 * j];
        float w1 = g_fwm[oc * CH + 2 * j + 1];
        uint32_t hi, lo;
        split2(w0, w1, hi, lo);
        Bh[oc * PB32 + j] = hi;
        Bl[oc * PB32 + j] = lo;
    }
    float bv[8];
    #pragma unroll
    for (int i = 0; i < 8; i++) bv[i] = bias[i];

    for (int it = 0; it < MIX_TILES; it++) {
        int tv = blockIdx.x * MIX_TILES + it;   // 0..4095
        int b  = tv >> 11;
        int p0 = (tv & 2047) * 128;

        // ---- stage Y tile (hi/lo bf16) with XOR-swizzled columns ----
        {
            const float* yb = g_y + (size_t)b * CH * VOX + p0 + t;
            int sw = (t >> 3) & 3;
            #pragma unroll 8
            for (int cp = 0; cp < 48; cp++) {
                float y0 = yb[(size_t)(2 * cp) * VOX];
                float y1 = yb[(size_t)(2 * cp + 1) * VOX];
                uint32_t hi, lo;
                split2(y0, y1, hi, lo);
                Ah[t * PA32 + (cp ^ sw)] = hi;
                Al[t * PA32 + (cp ^ sw)] = lo;
            }
        }
        __syncthreads();

        // ---- MMA: each warp computes 32 voxels x 96 oc ----
        int m0 = wid * 32;
        float acc[2][12][4];
        #pragma unroll
        for (int mt = 0; mt < 2; mt++)
            #pragma unroll
            for (int n = 0; n < 12; n++)
                #pragma unroll
                for (int i = 0; i < 4; i++) acc[mt][n][i] = 0.f;

        const uint32_t* Asrc[3] = { Ah, Al, Ah };
        const uint32_t* Bsrc[3] = { Bh, Bh, Bl };
        #pragma unroll 1
        for (int pass = 0; pass < 3; pass++) {
            const uint32_t* As = Asrc[pass];
            const uint32_t* Bs = Bsrc[pass];
            #pragma unroll
            for (int k = 0; k < 6; k++) {
                int c0 = 8 * k + q;
                uint32_t af[2][4];
                #pragma unroll
                for (int mt = 0; mt < 2; mt++) {
                    int row0 = m0 + mt * 16 + g;
                    int s0 = 2 * mt, s1 = 2 * mt + 1;
                    af[mt][0] = As[row0 * PA32       + (c0 ^ s0)];
                    af[mt][1] = As[(row0 + 8) * PA32 + (c0 ^ s1)];
                    af[mt][2] = As[row0 * PA32       + ((c0 + 4) ^ s0)];
                    af[mt][3] = As[(row0 + 8) * PA32 + ((c0 + 4) ^ s1)];
                }
                #pragma unroll
                for (int n = 0; n < 12; n++) {
                    const uint32_t* pb = Bs + (n * 8 + g) * PB32 + 8 * k + q;
                    uint32_t b0 = pb[0];
                    uint32_t b1 = pb[4];
                    mma16816(acc[0][n], af[0], b0, b1);
                    mma16816(acc[1][n], af[1], b0, b1);
                }
            }
        }

        // ---- stage D to smem (reuse A region), then coalesced writeback ----
        __syncthreads();
        float* D = (float*)(smem + OFF_AH);
        #pragma unroll
        for (int mt = 0; mt < 2; mt++) {
            int r1 = m0 + mt * 16 + g;
            #pragma unroll
            for (int n = 0; n < 12; n++) {
                int ocb = n * 8 + 2 * q;
                D[(ocb)     * PD + r1]     = acc[mt][n][0];
                D[(ocb + 1) * PD + r1]     = acc[mt][n][1];
                D[(ocb)     * PD + r1 + 8] = acc[mt][n][2];
                D[(ocb + 1) * PD + r1 + 8] = acc[mt][n][3];
            }
        }
        __syncthreads();

        float* ob = out + (size_t)b * CH * VOX + p0 + t;
        #pragma unroll
        for (int c = 0; c < CH; c++)
            ob[(size_t)c * VOX] = D[c * PD + t] + bv[c / 12];
        __syncthreads();
    }
}

// ---------------------------------------------------------------------------
extern "C" void kernel_launch(void* const* d_in, const int* in_sizes, int n_in,
                              void* d_out, int out_size)
{
    const float* x    = (const float*)d_in[0];
    const float* sp   = (const float*)d_in[1];
    const float* sph  = (const float*)d_in[2];
    const float* bw1  = (const float*)d_in[3];
    const float* bb1  = (const float*)d_in[4];
    const float* bw2  = (const float*)d_in[5];
    const float* bb2  = (const float*)d_in[6];
    const float* bw3  = (const float*)d_in[7];
    const float* fw1  = (const float*)d_in[8];
    const float* fb1  = (const float*)d_in[9];
    const float* fw2  = (const float*)d_in[10];
    const float* fb2  = (const float*)d_in[11];
    const float* fw3  = (const float*)d_in[12];
    const float* bias = (const float*)d_in[13];

    cudaFuncSetAttribute(mix_kernel, cudaFuncAttributeMaxDynamicSharedMemorySize,
                         MIX_SMEM_TOTAL);

    weights_kernel<<<13, 128>>>(sp, sph, bw1, bb1, bw2, bb2, bw3,
                                fw1, fb1, fw2, fb2, fw3);

    dim3 gA(128, CH, 2);
    conv_kernel<<<gA, 256>>>(x);

    mix_kernel<<<4096 / MIX_TILES, 128, MIX_SMEM_TOTAL>>>(bias, (float*)d_out);
}